// round 2
// baseline (speedup 1.0000x reference)
#include <cuda_runtime.h>

// Sliding-window (no-overlap chunk) attention, fp32 CUDA-core baseline.
// B=4, S=8192, H=16, D=64, window w=128, C=64 chunks.
// Outputs: out [B,S,H,64] then attn [B,S,H,384] concatenated in d_out.

constexpr int Bc = 4;
constexpr int Sc = 8192;
constexpr int Hc = 16;
constexpr int Dc = 64;
constexpr int Wn = 128;          // window / chunk size
constexpr int Cc = Sc / Wn;      // 64 chunks
constexpr int QT = 32;           // queries per block
constexpr int NT = 256;          // threads per block
constexpr int PRS = 384;         // score row stride (floats)

// smem layout (floats)
constexpr int OFF_Q  = 0;                  // Qs[64][32] transposed (d-major)
constexpr int OFF_KV = 2048;               // Ks[64][128] transposed OR Vs[128][64]
constexpr int OFF_P  = 2048 + 8192;        // Ps[32][384]
constexpr int SMEM_FLOATS = OFF_P + QT * PRS;   // 22528 floats = 88 KB

__global__ __launch_bounds__(NT, 2)
void swa_noovl_kernel(const float* __restrict__ q,
                      const float* __restrict__ k,
                      const float* __restrict__ v,
                      float* __restrict__ out,
                      float* __restrict__ attn)
{
    extern __shared__ float sm[];
    float* Qs = sm + OFF_Q;
    float* KV = sm + OFF_KV;
    float* Ps = sm + OFF_P;

    const int tid = threadIdx.x;
    const int c   = blockIdx.x >> 2;        // chunk
    const int qt  = blockIdx.x & 3;         // query sub-tile within chunk
    const int h   = blockIdx.y;
    const int b   = blockIdx.z;
    const int s0  = c * Wn + qt * QT;

    const size_t rowstride = (size_t)Hc * Dc;   // 1024 floats between seq positions

    // ---- Load Q tile transposed: Qs[d][y] (y = query row 0..31) ----
    {
        const float* qbase = q + ((size_t)b * Sc + s0) * rowstride + (size_t)h * Dc;
        int f = tid;
        #pragma unroll
        for (int i = 0; i < 2; i++) {          // 512 float4 total
            const int y = f & 31;
            const int g = f >> 5;              // dgroup 0..15
            const float4 val = *(const float4*)(qbase + (size_t)y * rowstride + g * 4);
            Qs[(4 * g + 0) * QT + y] = val.x;
            Qs[(4 * g + 1) * QT + y] = val.y;
            Qs[(4 * g + 2) * QT + y] = val.z;
            Qs[(4 * g + 3) * QT + y] = val.w;
            f += NT;
        }
    }

    // ================= QK^T : scores into Ps =================
    const int r0 = (tid >> 5) * 4;    // GEMM1: 8 row-groups
    const int c0 = (tid & 31) * 4;    //        32 col-groups

    for (int e = 0; e < 3; e++) {
        const int kc = c - 1 + e;
        const bool valid = (kc >= 0) && (kc < Cc);
        __syncthreads();   // previous GEMM done reading KV
        if (valid) {
            // load K chunk transposed: Ks[d][y]
            const float* kbase = k + ((size_t)b * Sc + (size_t)kc * Wn) * rowstride + (size_t)h * Dc;
            int f = tid;
            #pragma unroll
            for (int i = 0; i < 8; i++) {      // 2048 float4 total
                const int y = f & 127;
                const int g = f >> 7;          // dgroup 0..15
                const float4 val = *(const float4*)(kbase + (size_t)y * rowstride + g * 4);
                KV[(4 * g + 0) * Wn + y] = val.x;
                KV[(4 * g + 1) * Wn + y] = val.y;
                KV[(4 * g + 2) * Wn + y] = val.z;
                KV[(4 * g + 3) * Wn + y] = val.w;
                f += NT;
            }
        }
        __syncthreads();
        if (valid) {
            float acc[4][4];
            #pragma unroll
            for (int i = 0; i < 4; i++)
                #pragma unroll
                for (int j = 0; j < 4; j++) acc[i][j] = 0.0f;

            #pragma unroll 8
            for (int d = 0; d < Dc; d++) {
                const float4 a  = *(const float4*)(Qs + d * QT + r0);   // warp broadcast
                const float4 bb = *(const float4*)(KV + d * Wn + c0);   // conflict-free
                acc[0][0] += a.x * bb.x; acc[0][1] += a.x * bb.y;
                acc[0][2] += a.x * bb.z; acc[0][3] += a.x * bb.w;
                acc[1][0] += a.y * bb.x; acc[1][1] += a.y * bb.y;
                acc[1][2] += a.y * bb.z; acc[1][3] += a.y * bb.w;
                acc[2][0] += a.z * bb.x; acc[2][1] += a.z * bb.y;
                acc[2][2] += a.z * bb.z; acc[2][3] += a.z * bb.w;
                acc[3][0] += a.w * bb.x; acc[3][1] += a.w * bb.y;
                acc[3][2] += a.w * bb.z; acc[3][3] += a.w * bb.w;
            }
            #pragma unroll
            for (int i = 0; i < 4; i++) {
                float4 st = make_float4(acc[i][0], acc[i][1], acc[i][2], acc[i][3]);
                *(float4*)(Ps + (size_t)(r0 + i) * PRS + e * Wn + c0) = st;
            }
        } else {
            // padded neighbor: exact score 0 (matches reference zero-padding)
            const int r    = tid >> 3;
            const int col0 = (tid & 7) * 16;
            const float4 z = make_float4(0.f, 0.f, 0.f, 0.f);
            #pragma unroll
            for (int j = 0; j < 4; j++)
                *(float4*)(Ps + (size_t)r * PRS + e * Wn + col0 + 4 * j) = z;
        }
    }
    __syncthreads();

    // ================= softmax over 384 + write attn =================
    {
        const int lane = tid & 31;
        const int w    = tid >> 5;
        #pragma unroll
        for (int rr = 0; rr < 4; rr++) {
            const int r = w * 4 + rr;
            float* prow = Ps + (size_t)r * PRS;
            float4 vv[3];
            float m = -3.402823466e38f;
            #pragma unroll
            for (int kk = 0; kk < 3; kk++) {
                vv[kk] = *(const float4*)(prow + kk * Wn + lane * 4);
                m = fmaxf(m, fmaxf(fmaxf(vv[kk].x, vv[kk].y), fmaxf(vv[kk].z, vv[kk].w)));
            }
            #pragma unroll
            for (int o = 16; o; o >>= 1)
                m = fmaxf(m, __shfl_xor_sync(0xffffffffu, m, o));

            float ssum = 0.0f;
            #pragma unroll
            for (int kk = 0; kk < 3; kk++) {
                vv[kk].x = __expf(vv[kk].x - m);
                vv[kk].y = __expf(vv[kk].y - m);
                vv[kk].z = __expf(vv[kk].z - m);
                vv[kk].w = __expf(vv[kk].w - m);
                ssum += vv[kk].x + vv[kk].y + vv[kk].z + vv[kk].w;
            }
            #pragma unroll
            for (int o = 16; o; o >>= 1)
                ssum += __shfl_xor_sync(0xffffffffu, ssum, o);

            const float inv = 1.0f / ssum;
            float* arow = attn + (((size_t)b * Sc + (s0 + r)) * Hc + h) * (size_t)(3 * Wn);
            #pragma unroll
            for (int kk = 0; kk < 3; kk++) {
                vv[kk].x *= inv; vv[kk].y *= inv; vv[kk].z *= inv; vv[kk].w *= inv;
                *(float4*)(prow + kk * Wn + lane * 4) = vv[kk];       // keep normalized P
                *(float4*)(arow + kk * Wn + lane * 4) = vv[kk];       // coalesced output
            }
        }
    }

    // ================= P @ V_ext =================
    float acc2[2][4];
    #pragma unroll
    for (int i = 0; i < 2; i++)
        #pragma unroll
        for (int j = 0; j < 4; j++) acc2[i][j] = 0.0f;

    const int r0b = (tid >> 4) * 2;   // 16 row-groups of 2
    const int c0b = (tid & 15) * 4;   // 16 col-groups of 4

    for (int e = 0; e < 3; e++) {
        const int kc = c - 1 + e;
        if (kc < 0 || kc >= Cc) continue;   // uniform across block
        __syncthreads();   // prior GEMM2 done reading KV; softmax writes to Ps visible
        // load V chunk natural: Vs[y][d]
        const float* vbase = v + ((size_t)b * Sc + (size_t)kc * Wn) * rowstride + (size_t)h * Dc;
        int f = tid;
        #pragma unroll
        for (int i = 0; i < 8; i++) {
            const int y = f >> 4;
            const int g = f & 15;
            *(float4*)(KV + (size_t)y * Dc + g * 4) =
                *(const float4*)(vbase + (size_t)y * rowstride + g * 4);
            f += NT;
        }
        __syncthreads();

        const float* p0 = Ps + (size_t)(r0b + 0) * PRS + e * Wn;
        const float* p1 = Ps + (size_t)(r0b + 1) * PRS + e * Wn;
        #pragma unroll 8
        for (int y = 0; y < Wn; y++) {
            const float a0 = p0[y];
            const float a1 = p1[y];
            const float4 bb = *(const float4*)(KV + (size_t)y * Dc + c0b);
            acc2[0][0] += a0 * bb.x; acc2[0][1] += a0 * bb.y;
            acc2[0][2] += a0 * bb.z; acc2[0][3] += a0 * bb.w;
            acc2[1][0] += a1 * bb.x; acc2[1][1] += a1 * bb.y;
            acc2[1][2] += a1 * bb.z; acc2[1][3] += a1 * bb.w;
        }
    }

    // write out [B,S,H,64]
    {
        float* obase = out + ((size_t)b * Sc + s0) * rowstride + (size_t)h * Dc;
        #pragma unroll
        for (int i = 0; i < 2; i++) {
            float4 st = make_float4(acc2[i][0], acc2[i][1], acc2[i][2], acc2[i][3]);
            *(float4*)(obase + (size_t)(r0b + i) * rowstride + c0b) = st;
        }
    }
}

extern "C" void kernel_launch(void* const* d_in, const int* in_sizes, int n_in,
                              void* d_out, int out_size)
{
    const float* q = (const float*)d_in[0];
    const float* k = (const float*)d_in[1];
    const float* v = (const float*)d_in[2];
    float* out  = (float*)d_out;
    float* attn = out + (size_t)Bc * Sc * Hc * Dc;   // out first, then attn

    cudaFuncSetAttribute(swa_noovl_kernel,
                         cudaFuncAttributeMaxDynamicSharedMemorySize,
                         SMEM_FLOATS * (int)sizeof(float));

    dim3 grid(Cc * 4, Hc, Bc);   // (chunk*4 + qtile, head, batch)
    swa_noovl_kernel<<<grid, NT, SMEM_FLOATS * sizeof(float)>>>(q, k, v, out, attn);
}